// round 4
// baseline (speedup 1.0000x reference)
#include <cuda_runtime.h>
#include <cuda_bf16.h>
#include <cstdint>

// ============================================================================
// InfoNCE fused on sm_100 (plain target — no tcgen05):
//   prep:  fp32 normalize -> A = bf16(alpha*q_norm), B = bf16([d_n;q_n])
//   main:  mma.sync m16n8k16 bf16, A-frags register-resident, chunk-pipelined
//          ex2 epilogue overlapped with MMA issue, double-buffered B tiles
//   loss:  per-row log, deterministic two-level reduction (single kernel)
// ============================================================================

#define NQ      16384
#define DD      128
#define INV_T   14.285714285714286f     // 1/0.07
#define ALPHA   20.609929155556618f     // log2(e)/0.07
#define NTILE   32                      // 128-col tiles per CTA
#define SMEM_REQ (98304 + 1024)

static __device__ __align__(256) __nv_bfloat16 g_A[(size_t)NQ * DD];
static __device__ __align__(256) __nv_bfloat16 g_B[(size_t)2 * NQ * DD];
static __device__ float g_part[(size_t)NQ * 16];
static __device__ float g_diag[NQ];
static __device__ float g_red[64];
static __device__ unsigned g_cnt = 0;

// ------------------------------------------------------------- PTX helpers --
__device__ __forceinline__ uint32_t smem_u32(const void* p) {
    uint32_t a;
    asm("{ .reg .u64 t; cvta.to.shared.u64 t, %1; cvt.u32.u64 %0, t; }"
        : "=r"(a) : "l"(p));
    return a;
}
#define CPA16(dst, src) \
    asm volatile("cp.async.cg.shared.global [%0], [%1], 16;" :: "r"(dst), "l"(src))
#define CPA_COMMIT() asm volatile("cp.async.commit_group;" ::: "memory")
#define CPA_WAIT0()  asm volatile("cp.async.wait_group 0;" ::: "memory")

#define LDSM4(r, a) \
    asm volatile("ldmatrix.sync.aligned.m8n8.x4.shared.b16 {%0,%1,%2,%3}, [%4];" \
                 : "=r"((r)[0]), "=r"((r)[1]), "=r"((r)[2]), "=r"((r)[3]) : "r"(a))

#define MMA16816(c, a, b0, b1) \
    asm volatile("mma.sync.aligned.m16n8k16.row.col.f32.bf16.bf16.f32 " \
                 "{%0,%1,%2,%3}, {%4,%5,%6,%7}, {%8,%9}, {%0,%1,%2,%3};" \
                 : "+f"((c)[0]), "+f"((c)[1]), "+f"((c)[2]), "+f"((c)[3]) \
                 : "r"((a)[0]), "r"((a)[1]), "r"((a)[2]), "r"((a)[3]), \
                   "r"(b0), "r"(b1))

// zero-C variant: initializes the accumulator (no separate zero pass needed)
#define MMA16816Z(c, a, b0, b1) \
    asm volatile("mma.sync.aligned.m16n8k16.row.col.f32.bf16.bf16.f32 " \
                 "{%0,%1,%2,%3}, {%4,%5,%6,%7}, {%8,%9}, {%10,%10,%10,%10};" \
                 : "=f"((c)[0]), "=f"((c)[1]), "=f"((c)[2]), "=f"((c)[3]) \
                 : "r"((a)[0]), "r"((a)[1]), "r"((a)[2]), "r"((a)[3]), \
                   "r"(b0), "r"(b1), "f"(0.0f))

#define EX2(d, s) asm("ex2.approx.ftz.f32 %0, %1;" : "=f"(d) : "f"(s))

// SW128-style swizzle for a 128-row x 256B tile stored as blocked atoms.
__device__ __forceinline__ uint32_t swz(int row, int c) {
    return (uint32_t)(((row >> 3) + (c >> 3) * 16) * 1024
                      + (row & 7) * 128 + (((c & 7) ^ (row & 7)) * 16));
}

// ------------------------------------------------------------------ kernels --
__global__ void __launch_bounds__(256) k_prep(const float* __restrict__ q,
                                              const float* __restrict__ dm) {
    int wid = threadIdx.x >> 5, lane = threadIdx.x & 31;
    int row = blockIdx.x * 8 + wid;
    float4 fq = ((const float4*)(q  + (size_t)row * DD))[lane];
    float4 fd = ((const float4*)(dm + (size_t)row * DD))[lane];
    float sq = fq.x*fq.x + fq.y*fq.y + fq.z*fq.z + fq.w*fq.w;
    float sd = fd.x*fd.x + fd.y*fd.y + fd.z*fd.z + fd.w*fd.w;
    float dt = fq.x*fd.x + fq.y*fd.y + fq.z*fd.z + fq.w*fd.w;
    #pragma unroll
    for (int o = 16; o; o >>= 1) {
        sq += __shfl_xor_sync(~0u, sq, o);
        sd += __shfl_xor_sync(~0u, sd, o);
        dt += __shfl_xor_sync(~0u, dt, o);
    }
    float rq = rsqrtf(sq), rd = rsqrtf(sd);
    float sa = rq * ALPHA;
    __nv_bfloat162* pa = (__nv_bfloat162*)(g_A + (size_t)row * DD);
    pa[lane*2]   = __floats2bfloat162_rn(fq.x*sa, fq.y*sa);
    pa[lane*2+1] = __floats2bfloat162_rn(fq.z*sa, fq.w*sa);
    __nv_bfloat162* pbd = (__nv_bfloat162*)(g_B + (size_t)row * DD);
    pbd[lane*2]   = __floats2bfloat162_rn(fd.x*rd, fd.y*rd);
    pbd[lane*2+1] = __floats2bfloat162_rn(fd.z*rd, fd.w*rd);
    __nv_bfloat162* pbq = (__nv_bfloat162*)(g_B + (size_t)(NQ + row) * DD);
    pbq[lane*2]   = __floats2bfloat162_rn(fq.x*rq, fq.y*rq);
    pbq[lane*2+1] = __floats2bfloat162_rn(fq.z*rq, fq.w*rq);
    if (lane == 0) g_diag[row] = dt * rq * rd;
}

// exp2 + masked row-accumulate for one 16-col chunk (16 values per thread)
__device__ __forceinline__ void epi_chunk(const float* ac, int p, int tcwn,
                                          int cb, int wd0, int dbase,
                                          float* rs) {
    int lo = tcwn + 16 * p;
    bool maydiag = (lo < wd0 + 32) && (wd0 < lo + 16);
    if (!maydiag) {
        #pragma unroll
        for (int mi = 0; mi < 2; mi++)
            #pragma unroll
            for (int np = 0; np < 2; np++)
                #pragma unroll
                for (int k = 0; k < 4; k++) {
                    float e; EX2(e, ac[mi * 8 + np * 4 + k]);
                    rs[mi * 2 + (k >> 1)] += e;
                }
    } else {
        #pragma unroll
        for (int mi = 0; mi < 2; mi++)
            #pragma unroll
            for (int np = 0; np < 2; np++)
                #pragma unroll
                for (int k = 0; k < 4; k++) {
                    int col  = cb + (p * 2 + np) * 8 + (k & 1);
                    int dcol = dbase + mi * 16 + (k >> 1) * 8;
                    float e; EX2(e, ac[mi * 8 + np * 4 + k]);
                    if (col != dcol) rs[mi * 2 + (k >> 1)] += e;
                }
    }
}

__global__ void __launch_bounds__(256, 1) k_main() {
    extern __shared__ char smem_raw[];
    uint32_t s0 = (smem_u32(smem_raw) + 1023u) & ~1023u;
    const uint32_t sA = s0;
    uint32_t sB[2] = { s0 + 32768u, s0 + 65536u };

    int tid = threadIdx.x, wid = tid >> 5, lane = tid & 31;
    int rb = blockIdx.x >> 3, jq = blockIdx.x & 7;
    int wm = wid >> 1, wn = wid & 1;          // 4 x 2 warp grid
    int jcta = jq * 4096;

    // precomputed tile-load addresses (8 x 16B chunks per thread)
    uint32_t ldst[8], goff[8];
    #pragma unroll
    for (int tch = 0; tch < 8; tch++) {
        int idx = tid + tch * 256;
        int row = idx >> 4, c = idx & 15;
        ldst[tch] = swz(row, c);
        goff[tch] = (uint32_t)(row * 256 + c * 16);
    }
    const char* gA  = (const char*)g_A + (size_t)rb * 128 * 256;
    const char* gB0 = (const char*)g_B + (size_t)jcta * 256;

    #pragma unroll
    for (int tch = 0; tch < 8; tch++) CPA16(sA + ldst[tch], gA + goff[tch]);
    #pragma unroll
    for (int tch = 0; tch < 8; tch++) CPA16(sB[0] + ldst[tch], gB0 + goff[tch]);
    CPA_COMMIT();

    // ---- ldmatrix lane addressing ----
    int r7 = lane & 7, sel = lane >> 3;
    int acb = sel >> 1;                        // A k-half select
    int bcb = sel & 1;                         // B k-half select
    uint32_t abase[2]; int ax[2];
    #pragma unroll
    for (int mi = 0; mi < 2; mi++) {
        int row = wm * 32 + mi * 16 + r7 + (sel & 1) * 8;
        abase[mi] = sA + (uint32_t)((row >> 3) * 1024 + (row & 7) * 128);
        ax[mi] = row & 7;
    }
    uint32_t bbase[4]; int bx[4];
    #pragma unroll
    for (int p = 0; p < 4; p++) {
        int row = wn * 64 + p * 16 + r7 + (sel >> 1) * 8;
        bbase[p] = (uint32_t)((row >> 3) * 1024 + (row & 7) * 128);
        bx[p] = row & 7;
    }

    CPA_WAIT0();
    __syncthreads();

    // ---- A fragments: register-resident for the whole CTA lifetime ----
    uint32_t af[2][8][4];
    #pragma unroll
    for (int ks = 0; ks < 8; ks++) {
        int c = ks * 2 + acb;
        uint32_t coff = (uint32_t)((c >> 3) * 16384);
        #pragma unroll
        for (int mi = 0; mi < 2; mi++)
            LDSM4(af[mi][ks], abase[mi] + coff + (uint32_t)(((c & 7) ^ ax[mi]) * 16));
    }

    float rs[4] = {0.f, 0.f, 0.f, 0.f};
    int g = lane >> 2;
    int wd0 = NQ + rb * 128 + wm * 32;         // diag-row window base
    int dbase = wd0 + g;
    int cbl = jcta + wn * 64 + (lane & 3) * 2;

    float acc[2][16];
    const char* gBt = gB0 + 32768;

    #pragma unroll 1
    for (int t = 0; t < NTILE; t++) {
        int buf = t & 1;
        CPA_WAIT0();                 // B(t) resident in my thread's view
        __syncthreads();             // visible to all; buf^1 reads from t-1 done
        if (t + 1 < NTILE) {
            uint32_t d = sB[buf ^ 1];
            #pragma unroll
            for (int tch = 0; tch < 8; tch++) CPA16(d + ldst[tch], gBt + goff[tch]);
            gBt += 32768;
        }
        CPA_COMMIT();

        uint32_t sbb = sB[buf];
        int tcwn = jcta + t * 128 + wn * 64;
        int cb = cbl + t * 128;

        #pragma unroll
        for (int p = 0; p < 4; p++) {
            float* ac = acc[p & 1];
            #pragma unroll
            for (int ks = 0; ks < 8; ks++) {
                uint32_t bf[4];
                int c = ks * 2 + bcb;
                LDSM4(bf, sbb + (uint32_t)((c >> 3) * 16384) + bbase[p]
                          + (uint32_t)(((c & 7) ^ bx[p]) * 16));
                if (ks == 0) {
                    MMA16816Z(&ac[0],  af[0][0], bf[0], bf[1]);
                    MMA16816Z(&ac[4],  af[0][0], bf[2], bf[3]);
                    MMA16816Z(&ac[8],  af[1][0], bf[0], bf[1]);
                    MMA16816Z(&ac[12], af[1][0], bf[2], bf[3]);
                } else {
                    MMA16816(&ac[0],  af[0][ks], bf[0], bf[1]);
                    MMA16816(&ac[4],  af[0][ks], bf[2], bf[3]);
                    MMA16816(&ac[8],  af[1][ks], bf[0], bf[1]);
                    MMA16816(&ac[12], af[1][ks], bf[2], bf[3]);
                }
            }
            // overlap: epilogue of previous chunk runs under this chunk's MMAs
            if (p > 0) epi_chunk(acc[(p - 1) & 1], p - 1, tcwn, cb, wd0, dbase, rs);
        }
        epi_chunk(acc[1], 3, tcwn, cb, wd0, dbase, rs);
    }

    // reduce across the 4 lanes sharing each row
    #pragma unroll
    for (int i = 0; i < 4; i++) {
        rs[i] += __shfl_xor_sync(~0u, rs[i], 1);
        rs[i] += __shfl_xor_sync(~0u, rs[i], 2);
    }
    if ((lane & 3) == 0) {
        int rbase = rb * 128 + wm * 32 + g;
        int slot = jq * 2 + wn;
        g_part[(size_t)(rbase)      * 16 + slot] = rs[0];
        g_part[(size_t)(rbase + 8)  * 16 + slot] = rs[1];
        g_part[(size_t)(rbase + 16) * 16 + slot] = rs[2];
        g_part[(size_t)(rbase + 24) * 16 + slot] = rs[3];
    }
}

__global__ void __launch_bounds__(256) k_loss(float* out) {
    __shared__ float sm[256];
    int tid = threadIdx.x;
    int r = blockIdx.x * 256 + tid;
    const float* p = g_part + (size_t)r * 16;
    float v = 0.f;
    #pragma unroll
    for (int i = 0; i < 16; i++) v += p[i];
    sm[tid] = logf(v) - g_diag[r] * INV_T;
    __syncthreads();
    #pragma unroll
    for (int s = 128; s; s >>= 1) {
        if (tid < s) sm[tid] += sm[tid + s];
        __syncthreads();
    }
    if (tid == 0) {
        g_red[blockIdx.x] = sm[0];
        __threadfence();
        if (atomicAdd(&g_cnt, 1u) == 63u) {
            float s = 0.f;
            #pragma unroll
            for (int i = 0; i < 64; i++) s += g_red[i];   // fixed order: deterministic
            out[0] = s * (1.0f / NQ);
            g_cnt = 0;                                    // reset for next replay
        }
    }
}

// ------------------------------------------------------------------- launch --
extern "C" void kernel_launch(void* const* d_in, const int* in_sizes, int n_in,
                              void* d_out, int out_size) {
    const float* q  = (const float*)d_in[0];
    const float* dm = (const float*)d_in[1];
    cudaFuncSetAttribute(k_main, cudaFuncAttributeMaxDynamicSharedMemorySize, SMEM_REQ);
    k_prep<<<NQ / 8, 256>>>(q, dm);
    k_main<<<1024, 256, SMEM_REQ>>>();
    k_loss<<<64, 256>>>((float*)d_out);
}

// round 5
// speedup vs baseline: 1.1704x; 1.1704x over previous
#include <cuda_runtime.h>
#include <cuda_bf16.h>
#include <cstdint>

// ============================================================================
// InfoNCE fused on sm_100 (plain target — no tcgen05):
//   prep:  fp32 normalize -> A = bf16(alpha*q_norm), B = bf16([d_n;q_n])
//   main:  mma.sync m16n8k16 bf16, 2 CTAs/SM (forced <=128 regs), warp tile
//          processed in two 64-col halves, ex2 row-sum epilogue per half
//   loss:  per-row log, deterministic two-level reduction (single kernel)
// ============================================================================

#define NQ      16384
#define DD      128
#define INV_T   14.285714285714286f     // 1/0.07
#define ALPHA   20.609929155556618f     // log2(e)/0.07
#define NTILE   32                      // 128-col tiles per CTA
#define SMEM_REQ (98304 + 1024)

static __device__ __align__(256) __nv_bfloat16 g_A[(size_t)NQ * DD];
static __device__ __align__(256) __nv_bfloat16 g_B[(size_t)2 * NQ * DD];
static __device__ float g_part[(size_t)NQ * 16];
static __device__ float g_diag[NQ];
static __device__ float g_red[64];
static __device__ unsigned g_cnt = 0;

// ------------------------------------------------------------- PTX helpers --
__device__ __forceinline__ uint32_t smem_u32(const void* p) {
    uint32_t a;
    asm("{ .reg .u64 t; cvta.to.shared.u64 t, %1; cvt.u32.u64 %0, t; }"
        : "=r"(a) : "l"(p));
    return a;
}
#define CPA16(dst, src) \
    asm volatile("cp.async.cg.shared.global [%0], [%1], 16;" :: "r"(dst), "l"(src))
#define CPA_COMMIT() asm volatile("cp.async.commit_group;" ::: "memory")
#define CPA_WAIT0()  asm volatile("cp.async.wait_group 0;" ::: "memory")

#define LDSM4(r, a) \
    asm volatile("ldmatrix.sync.aligned.m8n8.x4.shared.b16 {%0,%1,%2,%3}, [%4];" \
                 : "=r"((r)[0]), "=r"((r)[1]), "=r"((r)[2]), "=r"((r)[3]) : "r"(a))

#define MMA16816(c, a, b0, b1) \
    asm volatile("mma.sync.aligned.m16n8k16.row.col.f32.bf16.bf16.f32 " \
                 "{%0,%1,%2,%3}, {%4,%5,%6,%7}, {%8,%9}, {%0,%1,%2,%3};" \
                 : "+f"((c)[0]), "+f"((c)[1]), "+f"((c)[2]), "+f"((c)[3]) \
                 : "r"((a)[0]), "r"((a)[1]), "r"((a)[2]), "r"((a)[3]), \
                   "r"(b0), "r"(b1))

#define MMA16816Z(c, a, b0, b1) \
    asm volatile("mma.sync.aligned.m16n8k16.row.col.f32.bf16.bf16.f32 " \
                 "{%0,%1,%2,%3}, {%4,%5,%6,%7}, {%8,%9}, {%10,%10,%10,%10};" \
                 : "=f"((c)[0]), "=f"((c)[1]), "=f"((c)[2]), "=f"((c)[3]) \
                 : "r"((a)[0]), "r"((a)[1]), "r"((a)[2]), "r"((a)[3]), \
                   "r"(b0), "r"(b1), "f"(0.0f))

#define EX2(d, s) asm("ex2.approx.ftz.f32 %0, %1;" : "=f"(d) : "f"(s))

// SW128-style swizzle for a 128-row x 256B tile stored as blocked atoms.
__device__ __forceinline__ uint32_t swz(int row, int c) {
    return (uint32_t)(((row >> 3) + (c >> 3) * 16) * 1024
                      + (row & 7) * 128 + (((c & 7) ^ (row & 7)) * 16));
}

// ------------------------------------------------------------------ kernels --
__global__ void __launch_bounds__(256) k_prep(const float* __restrict__ q,
                                              const float* __restrict__ dm) {
    int wid = threadIdx.x >> 5, lane = threadIdx.x & 31;
    int row = blockIdx.x * 8 + wid;
    float4 fq = ((const float4*)(q  + (size_t)row * DD))[lane];
    float4 fd = ((const float4*)(dm + (size_t)row * DD))[lane];
    float sq = fq.x*fq.x + fq.y*fq.y + fq.z*fq.z + fq.w*fq.w;
    float sd = fd.x*fd.x + fd.y*fd.y + fd.z*fd.z + fd.w*fd.w;
    float dt = fq.x*fd.x + fq.y*fd.y + fq.z*fd.z + fq.w*fd.w;
    #pragma unroll
    for (int o = 16; o; o >>= 1) {
        sq += __shfl_xor_sync(~0u, sq, o);
        sd += __shfl_xor_sync(~0u, sd, o);
        dt += __shfl_xor_sync(~0u, dt, o);
    }
    float rq = rsqrtf(sq), rd = rsqrtf(sd);
    float sa = rq * ALPHA;
    __nv_bfloat162* pa = (__nv_bfloat162*)(g_A + (size_t)row * DD);
    pa[lane*2]   = __floats2bfloat162_rn(fq.x*sa, fq.y*sa);
    pa[lane*2+1] = __floats2bfloat162_rn(fq.z*sa, fq.w*sa);
    __nv_bfloat162* pbd = (__nv_bfloat162*)(g_B + (size_t)row * DD);
    pbd[lane*2]   = __floats2bfloat162_rn(fd.x*rd, fd.y*rd);
    pbd[lane*2+1] = __floats2bfloat162_rn(fd.z*rd, fd.w*rd);
    __nv_bfloat162* pbq = (__nv_bfloat162*)(g_B + (size_t)(NQ + row) * DD);
    pbq[lane*2]   = __floats2bfloat162_rn(fq.x*rq, fq.y*rq);
    pbq[lane*2+1] = __floats2bfloat162_rn(fq.z*rq, fq.w*rq);
    if (lane == 0) g_diag[row] = dt * rq * rd;
}

__global__ void __launch_bounds__(256, 2) k_main() {
    extern __shared__ char smem_raw[];
    uint32_t s0 = (smem_u32(smem_raw) + 1023u) & ~1023u;
    const uint32_t sA = s0;
    uint32_t sB[2] = { s0 + 32768u, s0 + 65536u };

    int tid = threadIdx.x, wid = tid >> 5, lane = tid & 31;
    int rb = blockIdx.x >> 3, jq = blockIdx.x & 7;
    int wm = wid >> 1, wn = wid & 1;          // 4 x 2 warp grid
    int jcta = jq * 4096;

    // tile-load addressing (8 x 16B chunks per thread)
    uint32_t ldst[8], goff[8];
    #pragma unroll
    for (int tch = 0; tch < 8; tch++) {
        int idx = tid + tch * 256;
        int row = idx >> 4, c = idx & 15;
        ldst[tch] = swz(row, c);
        goff[tch] = (uint32_t)(row * 256 + c * 16);
    }
    const char* gA  = (const char*)g_A + (size_t)rb * 128 * 256;
    const char* gB0 = (const char*)g_B + (size_t)jcta * 256;

    #pragma unroll
    for (int tch = 0; tch < 8; tch++) CPA16(sA + ldst[tch], gA + goff[tch]);
    #pragma unroll
    for (int tch = 0; tch < 8; tch++) CPA16(sB[0] + ldst[tch], gB0 + goff[tch]);
    CPA_COMMIT();

    // ---- ldmatrix lane addressing ----
    int r7 = lane & 7, sel = lane >> 3;
    int acb = sel >> 1;                        // A k-half select
    int bcb = sel & 1;                         // B k-half select
    uint32_t abase[2]; int ax[2];
    #pragma unroll
    for (int mi = 0; mi < 2; mi++) {
        int row = wm * 32 + mi * 16 + r7 + (sel & 1) * 8;
        abase[mi] = sA + (uint32_t)((row >> 3) * 1024 + (row & 7) * 128);
        ax[mi] = row & 7;
    }
    uint32_t bbase[4]; int bx[4];
    #pragma unroll
    for (int p = 0; p < 4; p++) {
        int row = wn * 64 + p * 16 + r7 + (sel >> 1) * 8;
        bbase[p] = (uint32_t)((row >> 3) * 1024 + (row & 7) * 128);
        bx[p] = row & 7;
    }

    float rs[4] = {0.f, 0.f, 0.f, 0.f};
    int g = lane >> 2;
    int wd0 = NQ + rb * 128 + wm * 32;         // diag-row window base
    int dbase = wd0 + g;
    int cbl = jcta + wn * 64 + (lane & 3) * 2;
    const char* gBt = gB0 + 32768;

    #pragma unroll 1
    for (int t = 0; t < NTILE; t++) {
        int buf = t & 1;
        CPA_WAIT0();
        __syncthreads();
        if (t + 1 < NTILE) {
            uint32_t d = sB[buf ^ 1];
            #pragma unroll
            for (int tch = 0; tch < 8; tch++) CPA16(d + ldst[tch], gBt + goff[tch]);
            gBt += 32768;
        }
        CPA_COMMIT();

        uint32_t sbb = sB[buf];

        #pragma unroll
        for (int h = 0; h < 2; h++) {          // two 32-col halves of warp tile
            float acc[2][4][4];
            #pragma unroll
            for (int ks = 0; ks < 8; ks++) {
                uint32_t af[2][4], bf[2][4];
                {
                    int c = ks * 2 + acb;
                    uint32_t coff = (uint32_t)((c >> 3) * 16384);
                    LDSM4(af[0], abase[0] + coff + (uint32_t)(((c & 7) ^ ax[0]) * 16));
                    LDSM4(af[1], abase[1] + coff + (uint32_t)(((c & 7) ^ ax[1]) * 16));
                }
                {
                    int c = ks * 2 + bcb;
                    uint32_t coff = sbb + (uint32_t)((c >> 3) * 16384);
                    #pragma unroll
                    for (int pp = 0; pp < 2; pp++) {
                        int p = h * 2 + pp;
                        LDSM4(bf[pp], coff + bbase[p]
                                      + (uint32_t)(((c & 7) ^ bx[p]) * 16));
                    }
                }
                if (ks == 0) {
                    #pragma unroll
                    for (int mi = 0; mi < 2; mi++)
                        #pragma unroll
                        for (int nn = 0; nn < 4; nn++)
                            MMA16816Z(acc[mi][nn], af[mi],
                                      bf[nn >> 1][(nn & 1) * 2],
                                      bf[nn >> 1][(nn & 1) * 2 + 1]);
                } else {
                    #pragma unroll
                    for (int mi = 0; mi < 2; mi++)
                        #pragma unroll
                        for (int nn = 0; nn < 4; nn++)
                            MMA16816(acc[mi][nn], af[mi],
                                     bf[nn >> 1][(nn & 1) * 2],
                                     bf[nn >> 1][(nn & 1) * 2 + 1]);
                }
            }

            // ---- epilogue for this 32-col half ----
            int lo = jcta + t * 128 + wn * 64 + h * 32;
            bool maydiag = (lo < wd0 + 32) && (wd0 < lo + 32);
            if (!maydiag) {
                #pragma unroll
                for (int mi = 0; mi < 2; mi++)
                    #pragma unroll
                    for (int nn = 0; nn < 4; nn++)
                        #pragma unroll
                        for (int k = 0; k < 4; k++) {
                            float e; EX2(e, acc[mi][nn][k]);
                            rs[mi * 2 + (k >> 1)] += e;
                        }
            } else {
                int cb = cbl + t * 128 + h * 32;
                #pragma unroll
                for (int mi = 0; mi < 2; mi++)
                    #pragma unroll
                    for (int nn = 0; nn < 4; nn++)
                        #pragma unroll
                        for (int k = 0; k < 4; k++) {
                            int col  = cb + nn * 8 + (k & 1);
                            int dcol = dbase + mi * 16 + (k >> 1) * 8;
                            float e; EX2(e, acc[mi][nn][k]);
                            if (col != dcol) rs[mi * 2 + (k >> 1)] += e;
                        }
            }
        }
    }

    // reduce across the 4 lanes sharing each row
    #pragma unroll
    for (int i = 0; i < 4; i++) {
        rs[i] += __shfl_xor_sync(~0u, rs[i], 1);
        rs[i] += __shfl_xor_sync(~0u, rs[i], 2);
    }
    if ((lane & 3) == 0) {
        int rbase = rb * 128 + wm * 32 + g;
        int slot = jq * 2 + wn;
        g_part[(size_t)(rbase)      * 16 + slot] = rs[0];
        g_part[(size_t)(rbase + 8)  * 16 + slot] = rs[1];
        g_part[(size_t)(rbase + 16) * 16 + slot] = rs[2];
        g_part[(size_t)(rbase + 24) * 16 + slot] = rs[3];
    }
}

__global__ void __launch_bounds__(256) k_loss(float* out) {
    __shared__ float sm[256];
    int tid = threadIdx.x;
    int r = blockIdx.x * 256 + tid;
    const float* p = g_part + (size_t)r * 16;
    float v = 0.f;
    #pragma unroll
    for (int i = 0; i < 16; i++) v += p[i];
    sm[tid] = logf(v) - g_diag[r] * INV_T;
    __syncthreads();
    #pragma unroll
    for (int s = 128; s; s >>= 1) {
        if (tid < s) sm[tid] += sm[tid + s];
        __syncthreads();
    }
    if (tid == 0) {
        g_red[blockIdx.x] = sm[0];
        __threadfence();
        if (atomicAdd(&g_cnt, 1u) == 63u) {
            float s = 0.f;
            #pragma unroll
            for (int i = 0; i < 64; i++) s += g_red[i];   // fixed order: deterministic
            out[0] = s * (1.0f / NQ);
            g_cnt = 0;                                    // reset for next replay
        }
    }
}

// ------------------------------------------------------------------- launch --
extern "C" void kernel_launch(void* const* d_in, const int* in_sizes, int n_in,
                              void* d_out, int out_size) {
    const float* q  = (const float*)d_in[0];
    const float* dm = (const float*)d_in[1];
    cudaFuncSetAttribute(k_main, cudaFuncAttributeMaxDynamicSharedMemorySize, SMEM_REQ);
    k_prep<<<NQ / 8, 256>>>(q, dm);
    k_main<<<1024, 256, SMEM_REQ>>>();
    k_loss<<<64, 256>>>((float*)d_out);
}